// round 9
// baseline (speedup 1.0000x reference)
#include <cuda_runtime.h>
#include <cuda_fp16.h>

#define N_NODES 60000
#define N_EDGES 1200000
#define D 64
#define CAP 128                      // bucket capacity per node (max deg ~50)

// ---------------- scratch (no allocations allowed; zero-init at load) -------
__device__ int     g_fill[N_NODES];          // cursor; re-zeroed each replay
__device__ int     g_degv[N_NODES];          // PADDED degree (multiple of 8)
__device__ int     g_edges[N_NODES * CAP];   // bucketed src ids (+ sentinel pads)
__device__ float   g_dinv[N_NODES];          // 1/sqrt(max(deg,1))
__device__ float   g_dsq [N_NODES];          // sqrt(max(deg,1))
// row N_NODES is a permanent zero row (never written) used by sentinel pads
__device__ __half2 g_xs0[(N_NODES + 1) * 32];  // X0 * dinv (fp16)
__device__ __half2 g_xs1[(N_NODES + 1) * 32];  // X1 * dinv (fp16)

// ---------------- build: one atomic pass fills buckets; fused relu(X0) out --
__global__ void k_fill_relu(const int* __restrict__ src, const int* __restrict__ dst,
                            const float* __restrict__ feat, float* __restrict__ out,
                            int e, int n) {
    int i = blockIdx.x * blockDim.x + threadIdx.x;
    if (i < e) {
        int d   = dst[i];
        int pos = atomicAdd(&g_fill[d], 1);
        if (pos < CAP) g_edges[d * CAP + pos] = src[i];
    }
    if (i < n * 32) {                 // one float2 per thread: out[:,0:64]=relu(feat)
        int row  = i >> 5;
        int lane = i & 31;
        float2 f = ((const float2*)feat)[i];
        ((float2*)(out + (size_t)row * 192))[lane] =
            make_float2(fmaxf(f.x, 0.f), fmaxf(f.y, 0.f));
    }
}

// ---------------- scale: dinv/pad from cursor; xs0 = fp16(feat*dinv);
//                  pad bucket to multiple of 8 with sentinel N_NODES ---------
__global__ void k_scale(const float* __restrict__ feat, int n) {
    int i = blockIdx.x * blockDim.x + threadIdx.x;
    if (i >= n * 32) return;
    int row  = i >> 5;
    int lane = i & 31;
    int deg = g_fill[row];                        // all 32 lanes read it
    deg = min(deg, CAP);
    int pad = min((deg + 7) & ~7, CAP);
    float df = (float)(deg > 0 ? deg : 1);
    float di = rsqrtf(df);
    float2 f = ((const float2*)feat)[i];
    g_xs0[i] = __floats2half2_rn(f.x * di, f.y * di);
    if (lane < pad - deg)                         // <=7 sentinel pads
        g_edges[row * CAP + deg + lane] = N_NODES;
    __syncwarp();                                 // all lanes done with g_fill[row]
    if (lane == 0) {                              // warp owns the row exclusively
        g_degv[row] = pad;
        g_dinv[row] = di;
        g_dsq[row]  = sqrtf(df);
        g_fill[row] = 0;                          // ready for next graph replay
    }
}

// ---------------- gather: warp-per-node, padded buckets, no per-edge guard --
__device__ __forceinline__ float2 gather_bucket(int node, int pad, int lane,
                                                const __half2* __restrict__ xs) {
    const int* bucket = &g_edges[node * CAP];
    const __half2* xsl = xs + lane;               // per-lane base
    float2 acc = make_float2(0.f, 0.f);
    for (int j = 0; j < pad; j += 32) {
        int s   = __ldg(&bucket[j + lane]);       // always in-bounds (CAP region)
        int cnt = min(32, pad - j);               // multiple of 8
        for (int k = 0; k < cnt; k += 8) {
            #pragma unroll
            for (int kk = 0; kk < 8; kk++) {
                int sk = __shfl_sync(0xffffffffu, s, k + kk);
                float2 v = __half22float2(__ldg(xsl + sk * 32));
                acc.x += v.x;
                acc.y += v.y;
            }
        }
    }
    return acc;
}

// X1 = -rn*h + (rn-1)*X0 ; writes xs1 = fp16(X1*dinv), out[:,64:128]=relu(X1)
__global__ void k_apply1(const float* __restrict__ feat, const float* __restrict__ lam,
                         float* __restrict__ out, int n) {
    int w    = (blockIdx.x * blockDim.x + threadIdx.x) >> 5;
    int lane = threadIdx.x & 31;
    if (w >= n) return;
    float rn = 2.0f / __ldg(lam);
    float di = g_dinv[w];
    int  pad = __ldg(&g_degv[w]);
    float2 acc = gather_bucket(w, pad, lane, g_xs0);
    float2 x0 = ((const float2*)feat)[w * 32 + lane];
    float2 x1;
    x1.x = -rn * (acc.x * di) + x0.x * (rn - 1.0f);
    x1.y = -rn * (acc.y * di) + x0.y * (rn - 1.0f);
    g_xs1[w * 32 + lane] = __floats2half2_rn(x1.x * di, x1.y * di);
    ((float2*)(out + (size_t)w * 192 + 64))[lane] =
        make_float2(fmaxf(x1.x, 0.f), fmaxf(x1.y, 0.f));
}

// X2 = -2rn*h + 2(rn-1)*X1 - X0 ; X1 recovered as fp16(xs1)*sqrt(deg)
__global__ void k_apply2(const float* __restrict__ feat, const float* __restrict__ lam,
                         float* __restrict__ out, int n) {
    int w    = (blockIdx.x * blockDim.x + threadIdx.x) >> 5;
    int lane = threadIdx.x & 31;
    if (w >= n) return;
    float rn = 2.0f / __ldg(lam);
    float di = g_dinv[w];
    float ds = g_dsq[w];
    int  pad = __ldg(&g_degv[w]);
    float2 acc = gather_bucket(w, pad, lane, g_xs1);
    float2 x0  = ((const float2*)feat)[w * 32 + lane];
    float2 xs1 = __half22float2(g_xs1[w * 32 + lane]);
    float2 x1  = make_float2(xs1.x * ds, xs1.y * ds);
    float2 x2;
    x2.x = -2.0f * rn * (acc.x * di) + 2.0f * (rn - 1.0f) * x1.x - x0.x;
    x2.y = -2.0f * rn * (acc.y * di) + 2.0f * (rn - 1.0f) * x1.y - x0.y;
    ((float2*)(out + (size_t)w * 192 + 128))[lane] =
        make_float2(fmaxf(x2.x, 0.f), fmaxf(x2.y, 0.f));
}

// ---------------- launch ----------------
extern "C" void kernel_launch(void* const* d_in, const int* in_sizes, int n_in,
                              void* d_out, int out_size) {
    const float* feat = (const float*)d_in[0];
    const int*   src  = (const int*)d_in[1];
    const int*   dst  = (const int*)d_in[2];
    const float* lam  = (const float*)d_in[3];
    float* out = (float*)d_out;

    int n = in_sizes[0] / D;     // 60000
    int e = in_sizes[1];         // 1200000

    int fmax = (n * 32 > e) ? n * 32 : e;
    k_fill_relu<<<(fmax + 255) / 256, 256>>>(src, dst, feat, out, e, n);

    int fthreads = n * 32;
    k_scale <<<(fthreads + 255) / 256, 256>>>(feat, n);
    k_apply1<<<(fthreads + 255) / 256, 256>>>(feat, lam, out, n);
    k_apply2<<<(fthreads + 255) / 256, 256>>>(feat, lam, out, n);
}

// round 10
// speedup vs baseline: 1.0860x; 1.0860x over previous
#include <cuda_runtime.h>
#include <cuda_fp16.h>

#define N_NODES 60000
#define N_EDGES 1200000
#define D 64
#define CAP 128                      // bucket capacity per node (max deg ~50)

// ---------------- scratch (no allocations allowed; zero-init at load) -------
__device__ int     g_fill[N_NODES];          // cursor; re-zeroed each replay
__device__ int     g_degv[N_NODES];          // PADDED degree (multiple of 8)
__device__ int     g_edges[N_NODES * CAP];   // bucketed PRESCALED offs (src*32)
__device__ float   g_dinv[N_NODES];          // 1/sqrt(max(deg,1))
__device__ float   g_dsq [N_NODES];          // sqrt(max(deg,1))
// row N_NODES is a permanent zero row (never written) used by sentinel pads
__device__ __half2 g_xs0[(N_NODES + 1) * 32];  // X0 * dinv (fp16)
__device__ __half2 g_xs1[(N_NODES + 1) * 32];  // X1 * dinv (fp16)

// ---------------- build: one atomic pass fills buckets; fused relu(X0) out --
__global__ void k_fill_relu(const int* __restrict__ src, const int* __restrict__ dst,
                            const float* __restrict__ feat, float* __restrict__ out,
                            int e, int n) {
    int i = blockIdx.x * blockDim.x + threadIdx.x;
    if (i < e) {
        int d   = dst[i];
        int pos = atomicAdd(&g_fill[d], 1);
        if (pos < CAP) g_edges[d * CAP + pos] = src[i] * 32;   // half2-unit offset
    }
    if (i < n * 32) {                 // one float2 per thread: out[:,0:64]=relu(feat)
        int row  = i >> 5;
        int lane = i & 31;
        float2 f = ((const float2*)feat)[i];
        ((float2*)(out + (size_t)row * 192))[lane] =
            make_float2(fmaxf(f.x, 0.f), fmaxf(f.y, 0.f));
    }
}

// ---------------- scale: dinv/pad from cursor; xs0 = fp16(feat*dinv);
//                  pad bucket to multiple of 8 with sentinel zero-row --------
__global__ void k_scale(const float* __restrict__ feat, int n) {
    int i = blockIdx.x * blockDim.x + threadIdx.x;
    if (i >= n * 32) return;
    int row  = i >> 5;
    int lane = i & 31;
    int deg = g_fill[row];                        // all 32 lanes read it
    deg = min(deg, CAP);
    int pad = min((deg + 7) & ~7, CAP);
    float df = (float)(deg > 0 ? deg : 1);
    float di = rsqrtf(df);
    float2 f = ((const float2*)feat)[i];
    g_xs0[i] = __floats2half2_rn(f.x * di, f.y * di);
    if (lane < pad - deg)                         // <=7 sentinel pads
        g_edges[row * CAP + deg + lane] = N_NODES * 32;
    __syncwarp();                                 // all lanes done with g_fill[row]
    if (lane == 0) {                              // warp owns the row exclusively
        g_degv[row] = pad;
        g_dinv[row] = di;
        g_dsq[row]  = sqrtf(df);
        g_fill[row] = 0;                          // ready for next graph replay
    }
}

// ---------------- gather: warp-per-node, padded buckets,
//                  fp16 chunk-accumulate (8 edges) + fp32 flush --------------
__device__ __forceinline__ float2 gather_bucket(int node, int pad, int lane,
                                                const __half2* __restrict__ xs) {
    const int* bucket = &g_edges[node * CAP];
    const __half2* xsl = xs + lane;               // per-lane base
    float2 acc = make_float2(0.f, 0.f);
    const __half2 hz = __float2half2_rn(0.f);
    for (int j = 0; j < pad; j += 32) {
        int s   = __ldg(&bucket[j + lane]);       // prescaled offsets, in-bounds
        int cnt = min(32, pad - j);               // multiple of 8
        for (int k = 0; k < cnt; k += 8) {
            __half2 hacc = hz;
            #pragma unroll
            for (int kk = 0; kk < 8; kk++) {
                int sk = __shfl_sync(0xffffffffu, s, k + kk);
                hacc = __hadd2(hacc, __ldg(xsl + sk));
            }
            float2 fv = __half22float2(hacc);     // flush chunk to fp32
            acc.x += fv.x;
            acc.y += fv.y;
        }
    }
    return acc;
}

// X1 = -rn*h + (rn-1)*X0 ; writes xs1 = fp16(X1*dinv), out[:,64:128]=relu(X1)
__global__ void k_apply1(const float* __restrict__ feat, const float* __restrict__ lam,
                         float* __restrict__ out, int n) {
    int w    = (blockIdx.x * blockDim.x + threadIdx.x) >> 5;
    int lane = threadIdx.x & 31;
    if (w >= n) return;
    float rn = 2.0f / __ldg(lam);
    float di = g_dinv[w];
    int  pad = __ldg(&g_degv[w]);
    float2 acc = gather_bucket(w, pad, lane, g_xs0);
    float2 x0 = ((const float2*)feat)[w * 32 + lane];
    float2 x1;
    x1.x = -rn * (acc.x * di) + x0.x * (rn - 1.0f);
    x1.y = -rn * (acc.y * di) + x0.y * (rn - 1.0f);
    g_xs1[w * 32 + lane] = __floats2half2_rn(x1.x * di, x1.y * di);
    ((float2*)(out + (size_t)w * 192 + 64))[lane] =
        make_float2(fmaxf(x1.x, 0.f), fmaxf(x1.y, 0.f));
}

// X2 = -2rn*h + 2(rn-1)*X1 - X0 ; X1 recovered as fp16(xs1)*sqrt(deg)
__global__ void k_apply2(const float* __restrict__ feat, const float* __restrict__ lam,
                         float* __restrict__ out, int n) {
    int w    = (blockIdx.x * blockDim.x + threadIdx.x) >> 5;
    int lane = threadIdx.x & 31;
    if (w >= n) return;
    float rn = 2.0f / __ldg(lam);
    float di = g_dinv[w];
    float ds = g_dsq[w];
    int  pad = __ldg(&g_degv[w]);
    float2 acc = gather_bucket(w, pad, lane, g_xs1);
    float2 x0  = ((const float2*)feat)[w * 32 + lane];
    float2 xs1 = __half22float2(g_xs1[w * 32 + lane]);
    float2 x1  = make_float2(xs1.x * ds, xs1.y * ds);
    float2 x2;
    x2.x = -2.0f * rn * (acc.x * di) + 2.0f * (rn - 1.0f) * x1.x - x0.x;
    x2.y = -2.0f * rn * (acc.y * di) + 2.0f * (rn - 1.0f) * x1.y - x0.y;
    ((float2*)(out + (size_t)w * 192 + 128))[lane] =
        make_float2(fmaxf(x2.x, 0.f), fmaxf(x2.y, 0.f));
}

// ---------------- launch ----------------
extern "C" void kernel_launch(void* const* d_in, const int* in_sizes, int n_in,
                              void* d_out, int out_size) {
    const float* feat = (const float*)d_in[0];
    const int*   src  = (const int*)d_in[1];
    const int*   dst  = (const int*)d_in[2];
    const float* lam  = (const float*)d_in[3];
    float* out = (float*)d_out;

    int n = in_sizes[0] / D;     // 60000
    int e = in_sizes[1];         // 1200000

    int fmax = (n * 32 > e) ? n * 32 : e;
    k_fill_relu<<<(fmax + 255) / 256, 256>>>(src, dst, feat, out, e, n);

    int fthreads = n * 32;
    k_scale <<<(fthreads + 255) / 256, 256>>>(feat, n);
    k_apply1<<<(fthreads + 255) / 256, 256>>>(feat, lam, out, n);
    k_apply2<<<(fthreads + 255) / 256, 256>>>(feat, lam, out, n);
}